// round 9
// baseline (speedup 1.0000x reference)
#include <cuda_runtime.h>

typedef unsigned long long u64;

#define NITER 31
#define BLOCK 256

__device__ double   g_sum   = 0.0;
__device__ unsigned g_count = 0;

__device__ __forceinline__ u64 pk2(float a, float b) {
    u64 r; asm("mov.b64 %0, {%1, %2};" : "=l"(r) : "f"(a), "f"(b)); return r;
}
__device__ __forceinline__ void up2(u64 v, float &a, float &b) {
    asm("mov.b64 {%0, %1}, %2;" : "=f"(a), "=f"(b) : "l"(v));
}
__device__ __forceinline__ u64 ffma2(u64 a, u64 b, u64 c) {
    u64 d; asm("fma.rn.f32x2 %0, %1, %2, %3;" : "=l"(d) : "l"(a), "l"(b), "l"(c)); return d;
}
__device__ __forceinline__ u64 fmul2(u64 a, u64 b) {
    u64 d; asm("mul.rn.f32x2 %0, %1, %2;" : "=l"(d) : "l"(a), "l"(b)); return d;
}
__device__ __forceinline__ u64 fsub2(u64 a, u64 b) {
    u64 d; asm("sub.rn.f32x2 %0, %1, %2;" : "=l"(d) : "l"(a), "l"(b)); return d;
}
__device__ __forceinline__ u64 fadd2(u64 a, u64 b) {
    u64 d; asm("add.rn.f32x2 %0, %1, %2;" : "=l"(d) : "l"(a), "l"(b)); return d;
}
__device__ __forceinline__ float frcp_(float x) {
    float r; asm("rcp.approx.f32 %0, %1;" : "=f"(r) : "f"(x)); return r;
}
// Per-lane k = 2^(127 - exp(q)) so q*k lands in [1,2). Exact power of two
// (integer ops on the halves, alu pipe). Applied to BOTH p and q (common
// projective scale — value-preserving).
__device__ __forceinline__ u64 exp_scale(u64 q) {
    u64 k;
    asm("{\n\t"
        ".reg .b32 lo, hi, a, b;\n\t"
        "mov.b64 {lo, hi}, %1;\n\t"
        "and.b32 a, lo, 0x7F800000;\n\t"
        "and.b32 b, hi, 0x7F800000;\n\t"
        "sub.u32 a, 0x7F000000, a;\n\t"
        "sub.u32 b, 0x7F000000, b;\n\t"
        "mov.b64 %0, {a, b};\n\t"
        "}" : "=l"(k) : "l"(q));
    return k;
}

// Per-ray quadratic setup (|V_local| = 1, rotation invariance; only col 0 of R):
//   A = -c(1 - vlx^2),  B = vlx + 2c(plx*vlx - (P-T).V),
//   C = plx + c(plx^2 - |P-T|^2).
struct RayQ { float E, s, i4; };   // E = D+1, s0 = B, i4 = 1/(4A)

__device__ __forceinline__ RayQ setup_ray(
    float px, float py, float pz, float wx, float wy, float wz,
    float r00, float r10, float r20, float tx, float ty, float tz,
    float c, float mc, float twoc)
{
    float qx = px - tx, qy = py - ty, qz = pz - tz;
    float plx  = qx*r00 + qy*r10 + qz*r20;
    float vlx  = wx*r00 + wy*r10 + wz*r20;
    float ndot = fmaf(-qx, wx, fmaf(-qy, wy, -qz*wz));   // -(P-T).V
    float nn2  = fmaf(-qx, qx, fmaf(-qy, qy, -qz*qz));   // -|P-T|^2
    float A  = fmaf(vlx*vlx, c, mc);            // -c(1-vlx^2)
    float B  = fmaf(twoc, fmaf(plx, vlx, ndot), vlx);
    float C  = fmaf(c, fmaf(plx, plx, nn2), plx);
    if (A == 0.0f) { A = 1.0f; B = 1.0f; C = 0.0f; }     // degenerate guard
    RayQ o;
    float D = fmaf(A * C, -4.0f, B * B);        // D = B^2 - 4AC
    o.E  = D + 1.0f;
    o.s  = B;
    o.i4 = frcp_(4.0f * A);
    return o;
}

__global__ void __launch_bounds__(BLOCK)
lm_kernel(const float* __restrict__ P, const float* __restrict__ V,
          const float* __restrict__ R, const float* __restrict__ T,
          const float* __restrict__ Cs, const float* __restrict__ loss_in,
          float* __restrict__ out, int n, double invN)
{
    const int tid    = blockIdx.x * BLOCK + threadIdx.x;
    const int stride = gridDim.x * BLOCK;
    const int nchunks = (n + 7) >> 3;              // 8-ray chunks

    const float r00 = __ldg(R + 0), r10 = __ldg(R + 3), r20 = __ldg(R + 6);
    const float tx = __ldg(T + 0), ty = __ldg(T + 1), tz = __ldg(T + 2);
    const float c    = __ldg(Cs);
    const float mc   = -c;
    const float twoc = 2.0f * c;

    const u64 TWO2 = 0x4000000040000000ULL;  // (2, 2)
    const u64 ONE2 = 0x3F8000003F800000ULL;  // (1, 1)

    float ssum = 0.0f;

    for (int cid = tid; cid < nchunks; cid += stride) {
        const int base = cid * 8;

        RayQ rq[8];
        if (base + 8 <= n) {
            const float4* P4 = (const float4*)P;
            const float4* V4 = (const float4*)V;
            {
                float4 a0 = P4[6*cid + 0], a1 = P4[6*cid + 1], a2 = P4[6*cid + 2];
                float4 b0 = V4[6*cid + 0], b1 = V4[6*cid + 1], b2 = V4[6*cid + 2];
                rq[0] = setup_ray(a0.x,a0.y,a0.z, b0.x,b0.y,b0.z, r00,r10,r20, tx,ty,tz, c,mc,twoc);
                rq[1] = setup_ray(a0.w,a1.x,a1.y, b0.w,b1.x,b1.y, r00,r10,r20, tx,ty,tz, c,mc,twoc);
                rq[2] = setup_ray(a1.z,a1.w,a2.x, b1.z,b1.w,b2.x, r00,r10,r20, tx,ty,tz, c,mc,twoc);
                rq[3] = setup_ray(a2.y,a2.z,a2.w, b2.y,b2.z,b2.w, r00,r10,r20, tx,ty,tz, c,mc,twoc);
            }
            {
                float4 a0 = P4[6*cid + 3], a1 = P4[6*cid + 4], a2 = P4[6*cid + 5];
                float4 b0 = V4[6*cid + 3], b1 = V4[6*cid + 4], b2 = V4[6*cid + 5];
                rq[4] = setup_ray(a0.x,a0.y,a0.z, b0.x,b0.y,b0.z, r00,r10,r20, tx,ty,tz, c,mc,twoc);
                rq[5] = setup_ray(a0.w,a1.x,a1.y, b0.w,b1.x,b1.y, r00,r10,r20, tx,ty,tz, c,mc,twoc);
                rq[6] = setup_ray(a1.z,a1.w,a2.x, b1.z,b1.w,b2.x, r00,r10,r20, tx,ty,tz, c,mc,twoc);
                rq[7] = setup_ray(a2.y,a2.z,a2.w, b2.y,b2.z,b2.w, r00,r10,r20, tx,ty,tz, c,mc,twoc);
            }
        } else {
            #pragma unroll
            for (int k = 0; k < 8; ++k) {
                int i = base + k;
                if (i < n) {
                    rq[k] = setup_ray(P[3*i],P[3*i+1],P[3*i+2],
                                      V[3*i],V[3*i+1],V[3*i+2],
                                      r00,r10,r20, tx,ty,tz, c,mc,twoc);
                } else {
                    rq[k].E = 2.0f; rq[k].s = 1.0f; rq[k].i4 = 0.25f; // F ends 0
                }
            }
        }

        u64 E[4], p[4], q[4], I4[4];
        #pragma unroll
        for (int k = 0; k < 4; ++k) {
            E[k]  = pk2(rq[2*k].E,  rq[2*k+1].E);
            p[k]  = pk2(rq[2*k].s,  rq[2*k+1].s);   // s = p/q, q0 = 1
            q[k]  = ONE2;
            I4[k] = pk2(rq[2*k].i4, rq[2*k+1].i4);
        }

        // Projective LM (proven form): s' = s(s^2+E)/(2s^2+1)
        //   p' = p (p^2 + E q^2),  q' = q (2 p^2 + q^2)
        // Common exact power-of-two renorm every 2nd iteration.
        #pragma unroll
        for (int it = 0; it < NITER; ++it) {
            #pragma unroll
            for (int k = 0; k < 4; ++k) {
                u64 pp = fmul2(p[k], p[k]);
                u64 qq = fmul2(q[k], q[k]);
                u64 u  = ffma2(E[k], qq, pp);    // p^2 + E q^2
                u64 v  = ffma2(pp, TWO2, qq);    // 2 p^2 + q^2
                p[k] = fmul2(p[k], u);
                q[k] = fmul2(q[k], v);
            }
            if (it & 1) {
                #pragma unroll
                for (int k = 0; k < 4; ++k) {
                    u64 sc = exp_scale(q[k]);    // exact common scale
                    p[k] = fmul2(p[k], sc);
                    q[k] = fmul2(q[k], sc);
                }
            }
        }

        // Epilogue: s = p/q, F = (s^2 - D) i4 = (s^2 - E + 1) i4
        u64 ss = 0ULL;
        #pragma unroll
        for (int k = 0; k < 4; ++k) {
            float qa, qb; up2(q[k], qa, qb);
            u64 rq2 = pk2(frcp_(qa), frcp_(qb));
            u64 s  = fmul2(p[k], rq2);
            u64 qs = fmul2(s, s);
            u64 t  = fsub2(qs, E[k]);            // s^2 - D - 1
            u64 w  = fadd2(t, ONE2);             // s^2 - D
            u64 F  = fmul2(w, I4[k]);
            ss = ffma2(F, F, ss);
        }
        float sa, sb; up2(ss, sa, sb);
        ssum += sa + sb;
    }

    // Block tree reduction (float)
    #pragma unroll
    for (int o = 16; o > 0; o >>= 1)
        ssum += __shfl_xor_sync(0xffffffffu, ssum, o);
    __shared__ float wsum[BLOCK / 32];
    if ((threadIdx.x & 31) == 0) wsum[threadIdx.x >> 5] = ssum;
    __syncthreads();

    // Global double accumulation + last-block finalize (self-resetting for
    // identical behavior on every graph replay).
    if (threadIdx.x == 0) {
        float bsum = 0.0f;
        #pragma unroll
        for (int w = 0; w < BLOCK / 32; ++w) bsum += wsum[w];
        atomicAdd(&g_sum, (double)bsum);
        __threadfence();
        unsigned old = atomicAdd(&g_count, 1u);
        if (old == gridDim.x - 1) {
            __threadfence();
            double tot = g_sum;
            out[0] = (float)((double)loss_in[0] + tot * invN);
            g_sum = 0.0;
            __threadfence();
            g_count = 0;
        }
    }
}

extern "C" void kernel_launch(void* const* d_in, const int* in_sizes, int n_in,
                              void* d_out, int out_size)
{
    const float* P       = (const float*)d_in[0];
    const float* V       = (const float*)d_in[1];
    const float* R       = (const float*)d_in[2];
    const float* T       = (const float*)d_in[3];
    const float* c       = (const float*)d_in[4];
    const float* loss_in = (const float*)d_in[5];

    const int n = in_sizes[0] / 3;                 // number of rays

    // single resident wave of persistent grid-stride blocks (no prefetch)
    int nb = 0, sms = 0;
    cudaOccupancyMaxActiveBlocksPerMultiprocessor(&nb, lm_kernel, BLOCK, 0);
    cudaDeviceGetAttribute(&sms, cudaDevAttrMultiProcessorCount, 0);
    long long grid = (long long)(nb > 0 ? nb : 5) * (sms > 0 ? sms : 148);
    long long maxg = ((long long)((n + 7) >> 3) + BLOCK - 1) / BLOCK;
    if (maxg < 1) maxg = 1;
    if (grid > maxg) grid = maxg;

    lm_kernel<<<(int)grid, BLOCK>>>(P, V, R, T, c, loss_in,
                                    (float*)d_out, n, 1.0 / (double)n);
}